// round 1
// baseline (speedup 1.0000x reference)
#include <cuda_runtime.h>

#define BATCH 8
#define CIN 3
#define HW 320
#define C1 64
#define NCLS 2
#define PS 10
#define P2 100
#define NPR 32
#define NPATCH 1024
#define IMGS (BATCH*NCLS)

// scratch (device globals — no runtime allocation)
__device__ float g_t1[BATCH*C1*HW*HW];       // conv1 out  (210 MB)
__device__ float g_ini[BATCH*NCLS*HW*HW];    // conv2 out
__device__ float g_fea[BATCH*NCLS*HW*HW];    // 1x1 conv out
__device__ float g_Mt[P2*P2];                // (W2@W1) transposed: Mt[k][p]
__device__ float g_UI[IMGS*NPATCH*P2];
__device__ float g_UF[IMGS*NPATCH*P2];

// ---------------- M = w_lin2 @ w_lin1 (stored transposed) ----------------
__global__ void k_buildM(const float* __restrict__ w1, const float* __restrict__ w2) {
    int p = blockIdx.x;          // 0..99 output row of M
    int k = threadIdx.x;         // 0..127 (column)
    if (k >= P2) return;
    float acc = 0.f;
    for (int q = 0; q < 2*P2; ++q)
        acc += w2[p*2*P2 + q] * w1[q*P2 + k];
    g_Mt[k*P2 + p] = acc;
}

// ---------------- conv1: 7x7, 3->64, pad 3 ----------------
// block 16x16 threads, 32x32 spatial tile, each thread: 2x2 spatial x 16 oc
__global__ __launch_bounds__(256) void k_conv1(const float* __restrict__ x,
                                               const float* __restrict__ w,
                                               const float* __restrict__ b) {
    __shared__ float s_in[CIN][38][40];
    __shared__ float s_w[16*147];
    __shared__ float s_b[C1];
    int tx = threadIdx.x, ty = threadIdx.y;
    int tid = ty*16 + tx;
    int bz = blockIdx.z;
    int oy0 = blockIdx.y*32, ox0 = blockIdx.x*32;

    if (tid < C1) s_b[tid] = b[tid];
    for (int idx = tid; idx < CIN*38*38; idx += 256) {
        int ci = idx / (38*38); int r = idx % (38*38);
        int iy = r / 38, ix = r % 38;
        int gy = oy0 - 3 + iy, gx = ox0 - 3 + ix;
        float v = 0.f;
        if (gy >= 0 && gy < HW && gx >= 0 && gx < HW)
            v = x[((bz*CIN + ci)*HW + gy)*HW + gx];
        s_in[ci][iy][ix] = v;
    }

    for (int g = 0; g < 4; ++g) {
        __syncthreads();
        for (int idx = tid; idx < 16*147; idx += 256)
            s_w[idx] = w[g*16*147 + idx];
        __syncthreads();

        float a0[16], a1[16], a2[16], a3[16];
        #pragma unroll
        for (int o = 0; o < 16; ++o) {
            float bb = s_b[g*16 + o];
            a0[o] = bb; a1[o] = bb; a2[o] = bb; a3[o] = bb;
        }

        for (int ci = 0; ci < CIN; ++ci)
            for (int kh = 0; kh < 7; ++kh) {
                #pragma unroll
                for (int kw = 0; kw < 7; ++kw) {
                    float v0 = s_in[ci][ty+kh][tx+kw];
                    float v1 = s_in[ci][ty+kh][tx+16+kw];
                    float v2 = s_in[ci][ty+16+kh][tx+kw];
                    float v3 = s_in[ci][ty+16+kh][tx+16+kw];
                    int tap = (ci*7 + kh)*7 + kw;
                    #pragma unroll
                    for (int o = 0; o < 16; ++o) {
                        float wv = s_w[o*147 + tap];
                        a0[o] += v0*wv; a1[o] += v1*wv;
                        a2[o] += v2*wv; a3[o] += v3*wv;
                    }
                }
            }
        #pragma unroll
        for (int o = 0; o < 16; ++o) {
            int oc = g*16 + o;
            float* dst = &g_t1[(bz*C1 + oc)*HW*HW];
            dst[(oy0+ty)*HW    + ox0+tx]    = a0[o];
            dst[(oy0+ty)*HW    + ox0+tx+16] = a1[o];
            dst[(oy0+ty+16)*HW + ox0+tx]    = a2[o];
            dst[(oy0+ty+16)*HW + ox0+tx+16] = a3[o];
        }
    }
}

// ---------------- conv2 (3x3, 64->2, pad 1) + fm (1x1, 3->2, /4) ----------------
__global__ __launch_bounds__(256) void k_conv2_fea(const float* __restrict__ x,
        const float* __restrict__ w2, const float* __restrict__ b2,
        const float* __restrict__ wfm, const float* __restrict__ bfm) {
    __shared__ float s_t[8][34][36];
    __shared__ float s_w[2*C1*9];
    int tx = threadIdx.x, ty = threadIdx.y;
    int tid = ty*16 + tx;
    int bz = blockIdx.z;
    int oy0 = blockIdx.y*32, ox0 = blockIdx.x*32;

    for (int idx = tid; idx < 2*C1*9; idx += 256) s_w[idx] = w2[idx];

    float acc[2][4];
    #pragma unroll
    for (int c = 0; c < 2; ++c)
        #pragma unroll
        for (int j = 0; j < 4; ++j) acc[c][j] = 0.f;

    for (int cc = 0; cc < 8; ++cc) {
        __syncthreads();
        for (int idx = tid; idx < 8*34*34; idx += 256) {
            int ci = idx / (34*34); int r = idx % (34*34);
            int iy = r / 34, ix = r % 34;
            int gy = oy0 - 1 + iy, gx = ox0 - 1 + ix;
            float v = 0.f;
            if (gy >= 0 && gy < HW && gx >= 0 && gx < HW)
                v = g_t1[((bz*C1 + cc*8 + ci)*HW + gy)*HW + gx];
            s_t[ci][iy][ix] = v;
        }
        __syncthreads();
        for (int ci = 0; ci < 8; ++ci) {
            int cidx = cc*8 + ci;
            #pragma unroll
            for (int kh = 0; kh < 3; ++kh)
                #pragma unroll
                for (int kw = 0; kw < 3; ++kw) {
                    float v0 = s_t[ci][ty+kh][tx+kw];
                    float v1 = s_t[ci][ty+kh][tx+16+kw];
                    float v2 = s_t[ci][ty+16+kh][tx+kw];
                    float v3 = s_t[ci][ty+16+kh][tx+16+kw];
                    float w0 = s_w[cidx*9 + kh*3 + kw];
                    float w1 = s_w[576 + cidx*9 + kh*3 + kw];
                    acc[0][0] += v0*w0; acc[0][1] += v1*w0;
                    acc[0][2] += v2*w0; acc[0][3] += v3*w0;
                    acc[1][0] += v0*w1; acc[1][1] += v1*w1;
                    acc[1][2] += v2*w1; acc[1][3] += v3*w1;
                }
        }
    }

    int oys[4] = {oy0+ty, oy0+ty, oy0+ty+16, oy0+ty+16};
    int oxs[4] = {ox0+tx, ox0+tx+16, ox0+tx, ox0+tx+16};
    #pragma unroll
    for (int c = 0; c < 2; ++c) {
        float bb = b2[c];
        float f0 = wfm[c*3+0], f1 = wfm[c*3+1], f2 = wfm[c*3+2], fb = bfm[c];
        #pragma unroll
        for (int j = 0; j < 4; ++j) {
            int o = ((bz*2 + c)*HW + oys[j])*HW + oxs[j];
            g_ini[o] = acc[c][j] + bb;
            int xb = bz*CIN*HW*HW + oys[j]*HW + oxs[j];
            float s = x[xb]*f0 + x[xb + HW*HW]*f1 + x[xb + 2*HW*HW]*f2 + fb;
            g_fea[o] = s * 0.25f;
        }
    }
}

// ---------------- trans: out = relu(M @ v) per patch ----------------
// block = 128 thr, 16 patches; M (100x100) resident in smem
__global__ __launch_bounds__(128) void k_trans() {
    __shared__ float s_M[P2*P2];
    __shared__ float s_V[16][P2];
    int tid = threadIdx.x;
    int img = blockIdx.y;
    int l0 = blockIdx.x * 16;
    const float* src = (blockIdx.z == 0) ? g_ini : g_fea;
    float* dst = (blockIdx.z == 0) ? g_UI : g_UF;

    for (int idx = tid; idx < P2*P2; idx += 128) s_M[idx] = g_Mt[idx];
    for (int idx = tid; idx < 16*P2; idx += 128) {
        int pi = idx / P2, el = idx % P2;
        int l = l0 + pi;
        int ph = l / NPR, pw = l % NPR;
        int py = el / PS, px = el % PS;
        s_V[pi][el] = src[img*HW*HW + (ph*PS + py)*HW + (pw*PS + px)];
    }
    __syncthreads();

    if (tid < P2) {
        int p = tid;
        for (int pg = 0; pg < 4; ++pg) {
            float a0 = 0.f, a1 = 0.f, a2 = 0.f, a3 = 0.f;
            #pragma unroll 4
            for (int k = 0; k < P2; ++k) {
                float mv = s_M[k*P2 + p];
                a0 += mv * s_V[pg*4+0][k];
                a1 += mv * s_V[pg*4+1][k];
                a2 += mv * s_V[pg*4+2][k];
                a3 += mv * s_V[pg*4+3][k];
            }
            int base = img*NPATCH*P2 + (l0 + pg*4)*P2 + p;
            dst[base]        = fmaxf(a0, 0.f);
            dst[base + P2]   = fmaxf(a1, 0.f);
            dst[base + 2*P2] = fmaxf(a2, 0.f);
            dst[base + 3*P2] = fmaxf(a3, 0.f);
        }
    }
}

// ---------------- att: batched 1024x1024x100 NT-GEMM, /100 ----------------
// block 16x16, 64x64 tile, 4x4 per thread, K split in 2 chunks of 50
__global__ __launch_bounds__(256) void k_att(float* __restrict__ out) {
    __shared__ float s_A[64][51];
    __shared__ float s_B[64][51];
    int tx = threadIdx.x, ty = threadIdx.y;
    int tid = ty*16 + tx;
    int img = blockIdx.z;
    int l0 = blockIdx.y*64, m0 = blockIdx.x*64;
    const float* UI = g_UI + img*NPATCH*P2;
    const float* UF = g_UF + img*NPATCH*P2;

    float acc[4][4];
    #pragma unroll
    for (int i = 0; i < 4; ++i)
        #pragma unroll
        for (int j = 0; j < 4; ++j) acc[i][j] = 0.f;

    for (int ch = 0; ch < 2; ++ch) {
        int kb = ch*50;
        __syncthreads();
        for (int idx = tid; idx < 64*50; idx += 256) {
            int i = idx / 50, k = idx % 50;
            s_A[i][k] = UI[(l0 + i)*P2 + kb + k];
            s_B[i][k] = UF[(m0 + i)*P2 + kb + k];
        }
        __syncthreads();
        for (int k = 0; k < 50; ++k) {
            float a[4], bv[4];
            #pragma unroll
            for (int i = 0; i < 4; ++i) a[i] = s_A[4*ty + i][k];
            #pragma unroll
            for (int j = 0; j < 4; ++j) bv[j] = s_B[4*tx + j][k];
            #pragma unroll
            for (int i = 0; i < 4; ++i)
                #pragma unroll
                for (int j = 0; j < 4; ++j)
                    acc[i][j] += a[i]*bv[j];
        }
    }

    #pragma unroll
    for (int i = 0; i < 4; ++i) {
        float4 v = make_float4(acc[i][0]*0.01f, acc[i][1]*0.01f,
                               acc[i][2]*0.01f, acc[i][3]*0.01f);
        *(float4*)&out[((long)img*NPATCH + l0 + 4*ty + i)*NPATCH + m0 + 4*tx] = v;
    }
}

extern "C" void kernel_launch(void* const* d_in, const int* in_sizes, int n_in,
                              void* d_out, int out_size) {
    const float* x   = (const float*)d_in[0];
    const float* w1c = (const float*)d_in[1];
    const float* b1c = (const float*)d_in[2];
    const float* w2c = (const float*)d_in[3];
    const float* b2c = (const float*)d_in[4];
    const float* wfm = (const float*)d_in[5];
    const float* bfm = (const float*)d_in[6];
    const float* wl1 = (const float*)d_in[7];
    const float* wl2 = (const float*)d_in[8];
    float* out = (float*)d_out;

    k_buildM<<<P2, 128>>>(wl1, wl2);
    k_conv1<<<dim3(10,10,BATCH), dim3(16,16)>>>(x, w1c, b1c);
    k_conv2_fea<<<dim3(10,10,BATCH), dim3(16,16)>>>(x, w2c, b2c, wfm, bfm);
    k_trans<<<dim3(64, IMGS, 2), 128>>>();
    k_att<<<dim3(16,16,IMGS), dim3(16,16)>>>(out);
}